// round 7
// baseline (speedup 1.0000x reference)
#include <cuda_runtime.h>
#include <math.h>

#define BB 16
#define TT 12
#define NNODE 8600
#define HH 64
#define EE 128     // 2H
#define KK 66      // din_g = DIN + H
#define TM 32      // rows per block tile
#define ISTR 36    // padded sInp row stride (mult of 4 for 16B loads, !=32 to break conflicts)

// packed dual-fp32 FMA (Blackwell f32x2) — bitwise identical to 2x FFMA
#define FFMA2(acc, a, b) asm("fma.rn.f32x2 %0, %1, %2, %0;" : "+l"(acc) : "l"(a), "l"(b))

__device__ __forceinline__ unsigned long long pack2(float lo, float hi) {
    unsigned long long r;
    asm("mov.b64 %0, {%1, %2};" : "=l"(r) : "r"(__float_as_uint(lo)), "r"(__float_as_uint(hi)));
    return r;
}
__device__ __forceinline__ float lo32(unsigned long long v) {
    return __uint_as_float((unsigned)(v & 0xffffffffull));
}
__device__ __forceinline__ float hi32(unsigned long long v) {
    return __uint_as_float((unsigned)(v >> 32));
}

// ---------------- scratch (device globals: allowed) ----------------
__device__ float g_res[(long)BB * NNODE * EE];   // gate pre-activation "res" (70.4 MB)
__device__ float u_res[(long)BB * NNODE * HH];   // upd  pre-activation "res" (35.2 MB)
__device__ float g_agg[BB * EE];
__device__ float u_agg[BB * HH];

// ---------------- tiny per-step agg zeroing ----------------
__global__ void zero_agg_kernel() {
    int i = blockIdx.x * blockDim.x + threadIdx.x;
    if (i < BB * EE) g_agg[i] = 0.f;
    if (i < BB * HH) u_agg[i] = 0.f;
}

// ---------------- Kernel A: gate GEMMs + agg reduce ----------------
// inp = [x(2), state(64)] per row. Computes res = inp@Wa + bias,
// h = relu(inp@Wg + b) reduced over rows into g_agg[b][e].
// 256 threads: threads 0-127 -> Wa column e, threads 128-255 -> Wg column e.
extern "C" __global__ void __launch_bounds__(256, 2)
gate_mm_kernel(const float* __restrict__ x,
               const float* __restrict__ state_base, long bstride,
               const float* __restrict__ Wa, const float* __restrict__ ba,
               const float* __restrict__ Wg, const float* __restrict__ bg,
               int t)
{
    extern __shared__ float smem[];
    float* sW   = smem;                 // 2 * 66 * 128 = 16896 floats
    float* sb   = sW + 2 * KK * EE;     // 256 floats
    float* sInp = sb + 2 * EE;          // 66 * 36 floats (16B aligned: offset 17152 floats)

    const int tid = threadIdx.x;
    const int b   = blockIdx.y;
    const int n0  = blockIdx.x * TM;

    // vectorized weight staging (KK*EE = 8448 = 2112 float4s per matrix)
    {
        const float4* Wa4 = (const float4*)Wa;
        const float4* Wg4 = (const float4*)Wg;
        float4* sW4 = (float4*)sW;
        for (int i = tid; i < KK * EE / 4; i += 256) {
            sW4[i]                = Wa4[i];
            sW4[KK * EE / 4 + i]  = Wg4[i];
        }
    }
    if (tid < EE) { sb[tid] = ba[tid]; sb[EE + tid] = bg[tid]; }

    // x part (k = 0,1)
    for (int i = tid; i < TM * 2; i += 256) {
        int r = i >> 1, k = i & 1;
        int n = n0 + r;
        float v = 0.f;
        if (n < NNODE) v = x[(((long)b * TT + t) * NNODE + n) * 2 + k];
        sInp[k * ISTR + r] = v;
    }
    // state part (k = 2..65)
    for (int i = tid; i < TM * HH; i += 256) {
        int h = i & (HH - 1);
        int r = i >> 6;
        int n = n0 + r;
        float v = 0.f;
        if (n < NNODE) v = state_base[(long)b * bstride + (long)n * HH + h];
        sInp[(2 + h) * ISTR + r] = v;
    }
    __syncthreads();

    const int half = tid >> 7;         // 0: align (res), 1: gate (h)
    const int e    = tid & (EE - 1);
    const float* wcol = sW + half * (KK * EE) + e;

    unsigned long long acc[TM / 2];
    #pragma unroll
    for (int r = 0; r < TM / 2; r++) acc[r] = 0ull;

    #pragma unroll 2
    for (int k = 0; k < KK; k++) {
        float w = wcol[k * EE];
        unsigned long long ww = pack2(w, w);
        const ulonglong2* ip = (const ulonglong2*)(sInp + k * ISTR);
        #pragma unroll
        for (int rr = 0; rr < TM / 4; rr++) {
            ulonglong2 v = ip[rr];
            FFMA2(acc[rr * 2 + 0], v.x, ww);
            FFMA2(acc[rr * 2 + 1], v.y, ww);
        }
    }

    float bias = sb[half * EE + e];
    if (half == 0) {
        #pragma unroll
        for (int j = 0; j < TM / 2; j++) {
            int n = n0 + 2 * j;
            if (n < NNODE)     g_res[((long)b * NNODE + n)     * EE + e] = lo32(acc[j]) + bias;
            if (n + 1 < NNODE) g_res[((long)b * NNODE + n + 1) * EE + e] = hi32(acc[j]) + bias;
        }
    } else {
        int nmax = NNODE - n0;
        float s = 0.f;
        #pragma unroll
        for (int j = 0; j < TM / 2; j++) {
            if (2 * j     < nmax) s += fmaxf(lo32(acc[j]) + bias, 0.f);
            if (2 * j + 1 < nmax) s += fmaxf(hi32(acc[j]) + bias, 0.f);
        }
        atomicAdd(&g_agg[b * EE + e], s);
    }
}

// ---------------- Kernel B: gate combine(z) -> cand GEMMs + agg2 reduce ----------------
extern "C" __global__ void __launch_bounds__(128, 4)
upd_mm_kernel(const float* __restrict__ x,
              const float* __restrict__ state_base, long bstride,
              const float* __restrict__ g_aff_w, const float* __restrict__ g_aff_b,
              const float* __restrict__ g_node_w, const float* __restrict__ g_add_w,
              const float* __restrict__ Wa, const float* __restrict__ ba,
              const float* __restrict__ Wg, const float* __restrict__ bg,
              int t)
{
    __shared__ float sW[2 * KK * HH];          // 8448 floats
    __shared__ float sb[2 * HH];
    __shared__ __align__(16) float sInp[KK * ISTR];
    __shared__ float sagg[HH];
    __shared__ float sS[TM];

    const int tid = threadIdx.x;
    const int b   = blockIdx.y;
    const int n0  = blockIdx.x * TM;

    {
        const float4* Wa4 = (const float4*)Wa;
        const float4* Wg4 = (const float4*)Wg;
        float4* sW4 = (float4*)sW;
        for (int i = tid; i < KK * HH / 4; i += 128) {
            sW4[i]               = Wa4[i];
            sW4[KK * HH / 4 + i] = Wg4[i];
        }
    }
    if (tid < HH) { sb[tid] = ba[tid]; sb[HH + tid] = bg[tid]; sagg[tid] = g_agg[b * EE + tid]; }
    if (tid >= HH && tid < HH + TM) {
        int r = tid - HH;
        int n = n0 + r;
        sS[r] = (n < NNODE) ? g_add_w[n] * g_node_w[n] : 0.f;
    }
    for (int i = tid; i < TM * 2; i += 128) {
        int r = i >> 1, k = i & 1;
        int n = n0 + r;
        sInp[k * ISTR + r] = (n < NNODE) ? x[(((long)b * TT + t) * NNODE + n) * 2 + k] : 0.f;
    }
    __syncthreads();

    // cand state part: z * state
    for (int i = tid; i < TM * HH; i += 128) {
        int h = i & (HH - 1);
        int r = i >> 6;
        int n = n0 + r;
        float v = 0.f;
        if (n < NNODE) {
            long m = (long)b * NNODE + n;
            float pre = g_res[m * EE + h]
                      + g_aff_w[(long)n * EE + h] * (sS[r] * sagg[h])
                      + g_aff_b[(long)n * EE + h];
            float z = 1.f / (1.f + __expf(-pre));
            v = z * state_base[(long)b * bstride + (long)n * HH + h];
        }
        sInp[(2 + h) * ISTR + r] = v;
    }
    __syncthreads();

    const int half = tid >> 6;   // 0: upd_align (res2), 1: upd_w (h2)
    const int e    = tid & (HH - 1);
    const float* wcol = sW + half * (KK * HH) + e;

    unsigned long long acc[TM / 2];
    #pragma unroll
    for (int r = 0; r < TM / 2; r++) acc[r] = 0ull;

    #pragma unroll 2
    for (int k = 0; k < KK; k++) {
        float w = wcol[k * HH];
        unsigned long long ww = pack2(w, w);
        const ulonglong2* ip = (const ulonglong2*)(sInp + k * ISTR);
        #pragma unroll
        for (int rr = 0; rr < TM / 4; rr++) {
            ulonglong2 v = ip[rr];
            FFMA2(acc[rr * 2 + 0], v.x, ww);
            FFMA2(acc[rr * 2 + 1], v.y, ww);
        }
    }

    float bias = sb[half * HH + e];
    if (half == 0) {
        #pragma unroll
        for (int j = 0; j < TM / 2; j++) {
            int n = n0 + 2 * j;
            if (n < NNODE)     u_res[((long)b * NNODE + n)     * HH + e] = lo32(acc[j]) + bias;
            if (n + 1 < NNODE) u_res[((long)b * NNODE + n + 1) * HH + e] = hi32(acc[j]) + bias;
        }
    } else {
        int nmax = NNODE - n0;
        float s = 0.f;
        #pragma unroll
        for (int j = 0; j < TM / 2; j++) {
            if (2 * j     < nmax) s += fmaxf(lo32(acc[j]) + bias, 0.f);
            if (2 * j + 1 < nmax) s += fmaxf(hi32(acc[j]) + bias, 0.f);
        }
        atomicAdd(&u_agg[b * HH + e], s);
    }
}

// ---------------- Kernel C: final combine + output write (4 h per thread) ----------------
extern "C" __global__ void __launch_bounds__(256)
combine_kernel(const float* __restrict__ state_base, long bstride,
               const float* __restrict__ g_aff_w, const float* __restrict__ g_aff_b,
               const float* __restrict__ g_node_w, const float* __restrict__ g_add_w,
               const float* __restrict__ u_aff_w, const float* __restrict__ u_aff_b,
               const float* __restrict__ u_node_w, const float* __restrict__ u_add_w,
               float* __restrict__ out, int t)
{
    int i = blockIdx.x * 256 + threadIdx.x;          // i in [0, N * H/4)
    if (i >= NNODE * (HH / 4)) return;
    const int b = blockIdx.y;
    const int n = i >> 4;                            // H/4 = 16
    const int h = (i & 15) * 4;

    const long m = (long)b * NNODE + n;

    float sg = g_add_w[n] * g_node_w[n];
    float su = u_add_w[n] * u_node_w[n];

    float4 gr  = *(const float4*)(g_res   + m * EE + HH + h);
    float4 gaw = *(const float4*)(g_aff_w + (long)n * EE + HH + h);
    float4 gab = *(const float4*)(g_aff_b + (long)n * EE + HH + h);
    float4 gag = *(const float4*)(g_agg   + b * EE + HH + h);

    float4 ur  = *(const float4*)(u_res   + m * HH + h);
    float4 uaw = *(const float4*)(u_aff_w + (long)n * HH + h);
    float4 uab = *(const float4*)(u_aff_b + (long)n * HH + h);
    float4 uag = *(const float4*)(u_agg   + b * HH + h);

    float4 st  = *(const float4*)(state_base + (long)b * bstride + (long)n * HH + h);

    float4 hn;
    {
        float rp, r, hcp, hc;
        rp = gr.x + gaw.x * (sg * gag.x) + gab.x; r = 1.f / (1.f + __expf(-rp));
        hcp = ur.x + uaw.x * (su * uag.x) + uab.x; hc = tanhf(hcp);
        hn.x = r * st.x + (1.f - r) * hc;
        rp = gr.y + gaw.y * (sg * gag.y) + gab.y; r = 1.f / (1.f + __expf(-rp));
        hcp = ur.y + uaw.y * (su * uag.y) + uab.y; hc = tanhf(hcp);
        hn.y = r * st.y + (1.f - r) * hc;
        rp = gr.z + gaw.z * (sg * gag.z) + gab.z; r = 1.f / (1.f + __expf(-rp));
        hcp = ur.z + uaw.z * (su * uag.z) + uab.z; hc = tanhf(hcp);
        hn.z = r * st.z + (1.f - r) * hc;
        rp = gr.w + gaw.w * (sg * gag.w) + gab.w; r = 1.f / (1.f + __expf(-rp));
        hcp = ur.w + uaw.w * (su * uag.w) + uab.w; hc = tanhf(hcp);
        hn.w = r * st.w + (1.f - r) * hc;
    }

    *(float4*)(out + (((long)b * TT + t) * NNODE + n) * HH + h) = hn;
    if (t == TT - 1)
        *(float4*)(out + (long)BB * TT * NNODE * HH + m * HH + h) = hn;   // "last"
}

// ---------------- launch ----------------
extern "C" void kernel_launch(void* const* d_in, const int* in_sizes, int n_in,
                              void* d_out, int out_size)
{
    const float* x            = (const float*)d_in[0];
    const float* init_state   = (const float*)d_in[1];
    // d_in[2] node_emb0, d_in[3] node_emb1: unused by reference
    const float* gate_align_w = (const float*)d_in[4];
    const float* gate_align_b = (const float*)d_in[5];
    const float* gate_w       = (const float*)d_in[6];
    const float* gate_b       = (const float*)d_in[7];
    const float* gate_node_w  = (const float*)d_in[8];
    const float* gate_add_w   = (const float*)d_in[9];
    const float* gate_aff_w   = (const float*)d_in[10];
    const float* gate_aff_b   = (const float*)d_in[11];
    const float* upd_align_w  = (const float*)d_in[12];
    const float* upd_align_b  = (const float*)d_in[13];
    const float* upd_w        = (const float*)d_in[14];
    const float* upd_b        = (const float*)d_in[15];
    const float* upd_node_w   = (const float*)d_in[16];
    const float* upd_add_w    = (const float*)d_in[17];
    const float* upd_aff_w    = (const float*)d_in[18];
    const float* upd_aff_b    = (const float*)d_in[19];
    float* out = (float*)d_out;

    const int smemA = (2 * KK * EE + 2 * EE + KK * ISTR) * (int)sizeof(float); // 78,112 B
    cudaFuncSetAttribute(gate_mm_kernel, cudaFuncAttributeMaxDynamicSharedMemorySize, smemA);

    dim3 gridMM((NNODE + TM - 1) / TM, BB);                       // (269, 16)
    dim3 gridC((NNODE * (HH / 4) + 255) / 256, BB);               // (538, 16)

    for (int t = 0; t < TT; t++) {
        const float* sb_ = (t == 0) ? init_state : (out + (long)(t - 1) * NNODE * HH);
        long bstride     = (t == 0) ? (long)NNODE * HH : (long)TT * NNODE * HH;

        zero_agg_kernel<<<(BB * EE + 255) / 256, 256>>>();

        gate_mm_kernel<<<gridMM, 256, smemA>>>(x, sb_, bstride,
                                               gate_align_w, gate_align_b,
                                               gate_w, gate_b, t);

        upd_mm_kernel<<<gridMM, 128>>>(x, sb_, bstride,
                                       gate_aff_w, gate_aff_b, gate_node_w, gate_add_w,
                                       upd_align_w, upd_align_b, upd_w, upd_b, t);

        combine_kernel<<<gridC, 256>>>(sb_, bstride,
                                       gate_aff_w, gate_aff_b, gate_node_w, gate_add_w,
                                       upd_aff_w, upd_aff_b, upd_node_w, upd_add_w,
                                       out, t);
    }
}

// round 8
// speedup vs baseline: 1.0682x; 1.0682x over previous
#include <cuda_runtime.h>
#include <math.h>

#define BB 16
#define TT 12
#define NNODE 8600
#define HH 64
#define EE 128     // 2H
#define KK 66      // din_g = DIN + H
#define ROWS 64    // rows per block tile
#define ISR 68     // sInp row stride in floats (16B-multiple, 4-way STS conflict only)

// packed dual-fp32 FMA (Blackwell f32x2) — bitwise identical to 2x FFMA
#define FFMA2(acc, a, b) asm("fma.rn.f32x2 %0, %1, %2, %0;" : "+l"(acc) : "l"(a), "l"(b))

__device__ __forceinline__ unsigned long long pack2(float lo, float hi) {
    unsigned long long r;
    asm("mov.b64 %0, {%1, %2};" : "=l"(r) : "r"(__float_as_uint(lo)), "r"(__float_as_uint(hi)));
    return r;
}
__device__ __forceinline__ float lo32(unsigned long long v) {
    return __uint_as_float((unsigned)(v & 0xffffffffull));
}
__device__ __forceinline__ float hi32(unsigned long long v) {
    return __uint_as_float((unsigned)(v >> 32));
}

// ---------------- scratch (device globals: allowed) ----------------
__device__ float g_res[(long)BB * NNODE * EE];   // gate pre-activation "res" (70.4 MB)
__device__ float u_res[(long)BB * NNODE * HH];   // upd  pre-activation "res" (35.2 MB)
__device__ float g_agg[BB * EE];
__device__ float u_agg[BB * HH];

__global__ void zero_agg_kernel() {
    int i = blockIdx.x * blockDim.x + threadIdx.x;
    if (i < BB * EE) g_agg[i] = 0.f;
    if (i < BB * HH) u_agg[i] = 0.f;
}

// ---------------- Kernel A: gate GEMMs + agg reduce ----------------
// Block tile: 64 rows x 256 cols (cols 0-127: res via Wa, cols 128-255: h via Wg).
// 256 threads: cg = tid&63 -> col0 = 4*cg, rg = tid>>6 -> row0 = 16*rg.
// Each thread: 16 rows x 4 cols, rows packed pairwise in f32x2.
extern "C" __global__ void __launch_bounds__(256, 2)
gate_mm_kernel(const float* __restrict__ x,
               const float* __restrict__ state_base, long bstride,
               const float* __restrict__ Wa, const float* __restrict__ ba,
               const float* __restrict__ Wg, const float* __restrict__ bg,
               int t)
{
    extern __shared__ float smem[];
    float* sW   = smem;                 // 66 * 256 = 16896 floats  [k][c]
    float* sb   = sW + KK * 256;        // 256
    float* sInp = sb + 256;             // 66 * 68 floats, [k][row]

    const int tid = threadIdx.x;
    const int b   = blockIdx.y;
    const int n0  = blockIdx.x * ROWS;

    // stage weights: sW[k][c] ; c<128 -> Wa, c>=128 -> Wg
    {
        const float4* Wa4 = (const float4*)Wa;
        const float4* Wg4 = (const float4*)Wg;
        float4* sW4 = (float4*)sW;                 // row = 64 float4
        for (int i = tid; i < KK * EE / 4; i += 256) {
            int k = i >> 5, e4 = i & 31;
            sW4[k * 64 + e4]      = Wa4[i];
            sW4[k * 64 + 32 + e4] = Wg4[i];
        }
    }
    if (tid < EE) { sb[tid] = ba[tid]; sb[EE + tid] = bg[tid]; }

    // x part (k=0,1)
    if (tid < ROWS * 2) {
        int r = tid >> 1, k = tid & 1;
        int n = n0 + r;
        sInp[k * ISR + r] = (n < NNODE) ? x[(((long)b * TT + t) * NNODE + n) * 2 + k] : 0.f;
    }
    // state part (k=2..65)
    for (int i = tid; i < ROWS * HH; i += 256) {
        int h = i & (HH - 1);
        int r = i >> 6;
        int n = n0 + r;
        float v = 0.f;
        if (n < NNODE) v = state_base[(long)b * bstride + (long)n * HH + h];
        sInp[(2 + h) * ISR + r] = v;
    }
    __syncthreads();

    const int cg = tid & 63, rg = tid >> 6;
    const int col0 = cg * 4;
    const int row0 = rg * 16;

    unsigned long long acc[8][4];
    #pragma unroll
    for (int p = 0; p < 8; p++)
        #pragma unroll
        for (int c = 0; c < 4; c++) acc[p][c] = 0ull;

    const float* sWp = sW + col0;
    const float* sIp = sInp + row0;

    #pragma unroll 2
    for (int k = 0; k < KK; k++) {
        float4 w4 = *(const float4*)(sWp + k * 256);
        unsigned long long w0 = pack2(w4.x, w4.x);
        unsigned long long w1 = pack2(w4.y, w4.y);
        unsigned long long w2 = pack2(w4.z, w4.z);
        unsigned long long w3 = pack2(w4.w, w4.w);
        const ulonglong2* ip = (const ulonglong2*)(sIp + k * ISR);
        #pragma unroll
        for (int q = 0; q < 4; q++) {
            ulonglong2 v = ip[q];        // rows (4q,4q+1) and (4q+2,4q+3)
            FFMA2(acc[2*q  ][0], v.x, w0);
            FFMA2(acc[2*q  ][1], v.x, w1);
            FFMA2(acc[2*q  ][2], v.x, w2);
            FFMA2(acc[2*q  ][3], v.x, w3);
            FFMA2(acc[2*q+1][0], v.y, w0);
            FFMA2(acc[2*q+1][1], v.y, w1);
            FFMA2(acc[2*q+1][2], v.y, w2);
            FFMA2(acc[2*q+1][3], v.y, w3);
        }
    }

    float4 bias = *(const float4*)(sb + col0);
    const int nb = n0 + row0;

    if (cg < 32) {   // res half: e = col0
        #pragma unroll
        for (int p = 0; p < 8; p++) {
            int n = nb + 2 * p;
            if (n < NNODE) {
                float4 o = make_float4(lo32(acc[p][0]) + bias.x, lo32(acc[p][1]) + bias.y,
                                       lo32(acc[p][2]) + bias.z, lo32(acc[p][3]) + bias.w);
                *(float4*)(g_res + ((long)b * NNODE + n) * EE + col0) = o;
            }
            if (n + 1 < NNODE) {
                float4 o = make_float4(hi32(acc[p][0]) + bias.x, hi32(acc[p][1]) + bias.y,
                                       hi32(acc[p][2]) + bias.z, hi32(acc[p][3]) + bias.w);
                *(float4*)(g_res + ((long)b * NNODE + n + 1) * EE + col0) = o;
            }
        }
    } else {         // h half: relu + row-sum -> g_agg
        int e0 = col0 - 128;
        int nmax = NNODE - nb;
        float s0 = 0.f, s1 = 0.f, s2 = 0.f, s3 = 0.f;
        #pragma unroll
        for (int p = 0; p < 8; p++) {
            if (2 * p < nmax) {
                s0 += fmaxf(lo32(acc[p][0]) + bias.x, 0.f);
                s1 += fmaxf(lo32(acc[p][1]) + bias.y, 0.f);
                s2 += fmaxf(lo32(acc[p][2]) + bias.z, 0.f);
                s3 += fmaxf(lo32(acc[p][3]) + bias.w, 0.f);
            }
            if (2 * p + 1 < nmax) {
                s0 += fmaxf(hi32(acc[p][0]) + bias.x, 0.f);
                s1 += fmaxf(hi32(acc[p][1]) + bias.y, 0.f);
                s2 += fmaxf(hi32(acc[p][2]) + bias.z, 0.f);
                s3 += fmaxf(hi32(acc[p][3]) + bias.w, 0.f);
            }
        }
        atomicAdd(&g_agg[b * EE + 128 + e0 - 128 + 0], s0);   // = b*EE + e0
        atomicAdd(&g_agg[b * EE + e0 + 1], s1);
        atomicAdd(&g_agg[b * EE + e0 + 2], s2);
        atomicAdd(&g_agg[b * EE + e0 + 3], s3);
    }
}

// ---------------- Kernel B: z-combine -> cand GEMMs + agg2 ----------------
// Block tile: 64 rows x 128 cols (cols 0-63: res2 via Wa, 64-127: h2 via Wg).
// 128 threads: cg = tid&31 -> col0 = 4*cg, rg = tid>>5 -> row0 = 16*rg.
extern "C" __global__ void __launch_bounds__(128, 4)
upd_mm_kernel(const float* __restrict__ x,
              const float* __restrict__ state_base, long bstride,
              const float* __restrict__ g_aff_w, const float* __restrict__ g_aff_b,
              const float* __restrict__ g_node_w, const float* __restrict__ g_add_w,
              const float* __restrict__ Wa, const float* __restrict__ ba,
              const float* __restrict__ Wg, const float* __restrict__ bg,
              int t)
{
    extern __shared__ float smem[];
    float* sW   = smem;                 // 66 * 128 = 8448 floats [k][c]
    float* sb   = sW + KK * 128;        // 128
    float* sagg = sb + 128;             // 64
    float* sS   = sagg + 64;            // 64
    float* sInp = sS + 64;              // 66 * 68 floats (offset 8704: 16B aligned)

    const int tid = threadIdx.x;
    const int b   = blockIdx.y;
    const int n0  = blockIdx.x * ROWS;

    {
        const float4* Wa4 = (const float4*)Wa;
        const float4* Wg4 = (const float4*)Wg;
        float4* sW4 = (float4*)sW;                 // row = 32 float4
        for (int i = tid; i < KK * HH / 4; i += 128) {
            int k = i >> 4, e4 = i & 15;
            sW4[k * 32 + e4]      = Wa4[i];
            sW4[k * 32 + 16 + e4] = Wg4[i];
        }
    }
    if (tid < HH) { sb[tid] = ba[tid]; sb[HH + tid] = bg[tid]; sagg[tid] = g_agg[b * EE + tid]; }
    else {
        int r = tid - HH;                        // 0..63
        int n = n0 + r;
        sS[r] = (n < NNODE) ? g_add_w[n] * g_node_w[n] : 0.f;
    }
    // x part
    {
        int r = tid >> 1, k = tid & 1;           // 128 threads cover 64 rows x 2
        int n = n0 + r;
        sInp[k * ISR + r] = (n < NNODE) ? x[(((long)b * TT + t) * NNODE + n) * 2 + k] : 0.f;
    }
    __syncthreads();

    // cand state part: z * state
    for (int i = tid; i < ROWS * HH; i += 128) {
        int h = i & (HH - 1);
        int r = i >> 6;
        int n = n0 + r;
        float v = 0.f;
        if (n < NNODE) {
            long m = (long)b * NNODE + n;
            float pre = g_res[m * EE + h]
                      + g_aff_w[(long)n * EE + h] * (sS[r] * sagg[h])
                      + g_aff_b[(long)n * EE + h];
            float z = 1.f / (1.f + __expf(-pre));
            v = z * state_base[(long)b * bstride + (long)n * HH + h];
        }
        sInp[(2 + h) * ISR + r] = v;
    }
    __syncthreads();

    const int cg = tid & 31, rg = tid >> 5;
    const int col0 = cg * 4;
    const int row0 = rg * 16;

    unsigned long long acc[8][4];
    #pragma unroll
    for (int p = 0; p < 8; p++)
        #pragma unroll
        for (int c = 0; c < 4; c++) acc[p][c] = 0ull;

    const float* sWp = sW + col0;
    const float* sIp = sInp + row0;

    #pragma unroll 2
    for (int k = 0; k < KK; k++) {
        float4 w4 = *(const float4*)(sWp + k * 128);
        unsigned long long w0 = pack2(w4.x, w4.x);
        unsigned long long w1 = pack2(w4.y, w4.y);
        unsigned long long w2 = pack2(w4.z, w4.z);
        unsigned long long w3 = pack2(w4.w, w4.w);
        const ulonglong2* ip = (const ulonglong2*)(sIp + k * ISR);
        #pragma unroll
        for (int q = 0; q < 4; q++) {
            ulonglong2 v = ip[q];
            FFMA2(acc[2*q  ][0], v.x, w0);
            FFMA2(acc[2*q  ][1], v.x, w1);
            FFMA2(acc[2*q  ][2], v.x, w2);
            FFMA2(acc[2*q  ][3], v.x, w3);
            FFMA2(acc[2*q+1][0], v.y, w0);
            FFMA2(acc[2*q+1][1], v.y, w1);
            FFMA2(acc[2*q+1][2], v.y, w2);
            FFMA2(acc[2*q+1][3], v.y, w3);
        }
    }

    float4 bias = *(const float4*)(sb + col0);
    const int nb = n0 + row0;

    if (cg < 16) {   // res2 half: e = col0
        #pragma unroll
        for (int p = 0; p < 8; p++) {
            int n = nb + 2 * p;
            if (n < NNODE) {
                float4 o = make_float4(lo32(acc[p][0]) + bias.x, lo32(acc[p][1]) + bias.y,
                                       lo32(acc[p][2]) + bias.z, lo32(acc[p][3]) + bias.w);
                *(float4*)(u_res + ((long)b * NNODE + n) * HH + col0) = o;
            }
            if (n + 1 < NNODE) {
                float4 o = make_float4(hi32(acc[p][0]) + bias.x, hi32(acc[p][1]) + bias.y,
                                       hi32(acc[p][2]) + bias.z, hi32(acc[p][3]) + bias.w);
                *(float4*)(u_res + ((long)b * NNODE + n + 1) * HH + col0) = o;
            }
        }
    } else {
        int e0 = col0 - 64;
        int nmax = NNODE - nb;
        float s0 = 0.f, s1 = 0.f, s2 = 0.f, s3 = 0.f;
        #pragma unroll
        for (int p = 0; p < 8; p++) {
            if (2 * p < nmax) {
                s0 += fmaxf(lo32(acc[p][0]) + bias.x, 0.f);
                s1 += fmaxf(lo32(acc[p][1]) + bias.y, 0.f);
                s2 += fmaxf(lo32(acc[p][2]) + bias.z, 0.f);
                s3 += fmaxf(lo32(acc[p][3]) + bias.w, 0.f);
            }
            if (2 * p + 1 < nmax) {
                s0 += fmaxf(hi32(acc[p][0]) + bias.x, 0.f);
                s1 += fmaxf(hi32(acc[p][1]) + bias.y, 0.f);
                s2 += fmaxf(hi32(acc[p][2]) + bias.z, 0.f);
                s3 += fmaxf(hi32(acc[p][3]) + bias.w, 0.f);
            }
        }
        atomicAdd(&u_agg[b * HH + e0 + 0], s0);
        atomicAdd(&u_agg[b * HH + e0 + 1], s1);
        atomicAdd(&u_agg[b * HH + e0 + 2], s2);
        atomicAdd(&u_agg[b * HH + e0 + 3], s3);
    }
}

// ---------------- Kernel C: final combine + output write (4 h per thread) ----------------
extern "C" __global__ void __launch_bounds__(256)
combine_kernel(const float* __restrict__ state_base, long bstride,
               const float* __restrict__ g_aff_w, const float* __restrict__ g_aff_b,
               const float* __restrict__ g_node_w, const float* __restrict__ g_add_w,
               const float* __restrict__ u_aff_w, const float* __restrict__ u_aff_b,
               const float* __restrict__ u_node_w, const float* __restrict__ u_add_w,
               float* __restrict__ out, int t)
{
    int i = blockIdx.x * 256 + threadIdx.x;          // i in [0, N * H/4)
    if (i >= NNODE * (HH / 4)) return;
    const int b = blockIdx.y;
    const int n = i >> 4;
    const int h = (i & 15) * 4;

    const long m = (long)b * NNODE + n;

    float sg = g_add_w[n] * g_node_w[n];
    float su = u_add_w[n] * u_node_w[n];

    float4 gr  = *(const float4*)(g_res   + m * EE + HH + h);
    float4 gaw = *(const float4*)(g_aff_w + (long)n * EE + HH + h);
    float4 gab = *(const float4*)(g_aff_b + (long)n * EE + HH + h);
    float4 gag = *(const float4*)(g_agg   + b * EE + HH + h);

    float4 ur  = *(const float4*)(u_res   + m * HH + h);
    float4 uaw = *(const float4*)(u_aff_w + (long)n * HH + h);
    float4 uab = *(const float4*)(u_aff_b + (long)n * HH + h);
    float4 uag = *(const float4*)(u_agg   + b * HH + h);

    float4 st  = *(const float4*)(state_base + (long)b * bstride + (long)n * HH + h);

    float4 hn;
    {
        float rp, r, hcp, hc;
        rp = gr.x + gaw.x * (sg * gag.x) + gab.x; r = 1.f / (1.f + __expf(-rp));
        hcp = ur.x + uaw.x * (su * uag.x) + uab.x; hc = tanhf(hcp);
        hn.x = r * st.x + (1.f - r) * hc;
        rp = gr.y + gaw.y * (sg * gag.y) + gab.y; r = 1.f / (1.f + __expf(-rp));
        hcp = ur.y + uaw.y * (su * uag.y) + uab.y; hc = tanhf(hcp);
        hn.y = r * st.y + (1.f - r) * hc;
        rp = gr.z + gaw.z * (sg * gag.z) + gab.z; r = 1.f / (1.f + __expf(-rp));
        hcp = ur.z + uaw.z * (su * uag.z) + uab.z; hc = tanhf(hcp);
        hn.z = r * st.z + (1.f - r) * hc;
        rp = gr.w + gaw.w * (sg * gag.w) + gab.w; r = 1.f / (1.f + __expf(-rp));
        hcp = ur.w + uaw.w * (su * uag.w) + uab.w; hc = tanhf(hcp);
        hn.w = r * st.w + (1.f - r) * hc;
    }

    *(float4*)(out + (((long)b * TT + t) * NNODE + n) * HH + h) = hn;
    if (t == TT - 1)
        *(float4*)(out + (long)BB * TT * NNODE * HH + m * HH + h) = hn;
}

// ---------------- launch ----------------
extern "C" void kernel_launch(void* const* d_in, const int* in_sizes, int n_in,
                              void* d_out, int out_size)
{
    const float* x            = (const float*)d_in[0];
    const float* init_state   = (const float*)d_in[1];
    const float* gate_align_w = (const float*)d_in[4];
    const float* gate_align_b = (const float*)d_in[5];
    const float* gate_w       = (const float*)d_in[6];
    const float* gate_b       = (const float*)d_in[7];
    const float* gate_node_w  = (const float*)d_in[8];
    const float* gate_add_w   = (const float*)d_in[9];
    const float* gate_aff_w   = (const float*)d_in[10];
    const float* gate_aff_b   = (const float*)d_in[11];
    const float* upd_align_w  = (const float*)d_in[12];
    const float* upd_align_b  = (const float*)d_in[13];
    const float* upd_w        = (const float*)d_in[14];
    const float* upd_b        = (const float*)d_in[15];
    const float* upd_node_w   = (const float*)d_in[16];
    const float* upd_add_w    = (const float*)d_in[17];
    const float* upd_aff_w    = (const float*)d_in[18];
    const float* upd_aff_b    = (const float*)d_in[19];
    float* out = (float*)d_out;

    const int smemA = (KK * 256 + 256 + KK * ISR) * (int)sizeof(float);              // 86,560 B
    const int smemB = (KK * 128 + 128 + 64 + 64 + KK * ISR) * (int)sizeof(float);    // 52,768 B
    cudaFuncSetAttribute(gate_mm_kernel, cudaFuncAttributeMaxDynamicSharedMemorySize, smemA);
    cudaFuncSetAttribute(upd_mm_kernel,  cudaFuncAttributeMaxDynamicSharedMemorySize, smemB);

    dim3 gridMM((NNODE + ROWS - 1) / ROWS, BB);                   // (135, 16)
    dim3 gridC((NNODE * (HH / 4) + 255) / 256, BB);               // (538, 16)

    for (int t = 0; t < TT; t++) {
        const float* sb_ = (t == 0) ? init_state : (out + (long)(t - 1) * NNODE * HH);
        long bstride     = (t == 0) ? (long)NNODE * HH : (long)TT * NNODE * HH;

        zero_agg_kernel<<<(BB * EE + 255) / 256, 256>>>();

        gate_mm_kernel<<<gridMM, 256, smemA>>>(x, sb_, bstride,
                                               gate_align_w, gate_align_b,
                                               gate_w, gate_b, t);

        upd_mm_kernel<<<gridMM, 128, smemB>>>(x, sb_, bstride,
                                              gate_aff_w, gate_aff_b, gate_node_w, gate_add_w,
                                              upd_align_w, upd_align_b, upd_w, upd_b, t);

        combine_kernel<<<gridC, 256>>>(sb_, bstride,
                                       gate_aff_w, gate_aff_b, gate_node_w, gate_add_w,
                                       upd_aff_w, upd_aff_b, upd_node_w, upd_add_w,
                                       out, t);
    }
}

// round 9
// speedup vs baseline: 1.0721x; 1.0036x over previous
#include <cuda_runtime.h>
#include <math.h>

#define BB 16
#define TT 12
#define NNODE 8600
#define HH 64
#define EE 128     // 2H
#define KK 66      // din_g = DIN + H
#define ROWS 64    // rows per block tile
#define ISR 68     // sInp row stride in floats (16B-multiple, 4-way STS conflict only)

// packed dual-fp32 FMA (Blackwell f32x2) — bitwise identical to 2x FFMA
#define FFMA2(acc, a, b) asm("fma.rn.f32x2 %0, %1, %2, %0;" : "+l"(acc) : "l"(a), "l"(b))

__device__ __forceinline__ unsigned long long pack2(float lo, float hi) {
    unsigned long long r;
    asm("mov.b64 %0, {%1, %2};" : "=l"(r) : "r"(__float_as_uint(lo)), "r"(__float_as_uint(hi)));
    return r;
}
__device__ __forceinline__ float lo32(unsigned long long v) {
    return __uint_as_float((unsigned)(v & 0xffffffffull));
}
__device__ __forceinline__ float hi32(unsigned long long v) {
    return __uint_as_float((unsigned)(v >> 32));
}

// ---------------- scratch (device globals: allowed) ----------------
__device__ float g_res[(long)BB * NNODE * EE];   // gate pre-activation "res" (70.4 MB)
__device__ float u_res[(long)BB * NNODE * HH];   // upd  pre-activation "res" (35.2 MB)
__device__ float g_agg[BB * EE];
__device__ float u_agg[BB * HH];

__global__ void zero_agg_kernel() {
    int i = blockIdx.x * blockDim.x + threadIdx.x;
    if (i < BB * EE) g_agg[i] = 0.f;
    if (i < BB * HH) u_agg[i] = 0.f;
}

// ---------------- Kernel A: gate GEMMs + agg reduce ----------------
// Block tile: 64 rows x 256 cols (cols 0-127: res via Wa, cols 128-255: h via Wg).
// 256 threads: cg = tid&63 -> col0 = 4*cg, rg = tid>>6 -> row0 = 16*rg.
// Each thread: 16 rows x 4 cols, rows packed pairwise in f32x2.
extern "C" __global__ void __launch_bounds__(256, 2)
gate_mm_kernel(const float* __restrict__ x,
               const float* __restrict__ state_base, long bstride,
               const float* __restrict__ Wa, const float* __restrict__ ba,
               const float* __restrict__ Wg, const float* __restrict__ bg,
               int t)
{
    extern __shared__ float smem[];
    float* sW   = smem;                 // 66 * 256 = 16896 floats  [k][c]
    float* sb   = sW + KK * 256;        // 256
    float* sInp = sb + 256;             // 66 * 68 floats, [k][row]

    const int tid = threadIdx.x;
    const int b   = blockIdx.y;
    const int n0  = blockIdx.x * ROWS;

    // stage weights: sW[k][c] ; c<128 -> Wa, c>=128 -> Wg
    {
        const float4* Wa4 = (const float4*)Wa;
        const float4* Wg4 = (const float4*)Wg;
        float4* sW4 = (float4*)sW;                 // row = 64 float4
        for (int i = tid; i < KK * EE / 4; i += 256) {
            int k = i >> 5, e4 = i & 31;
            sW4[k * 64 + e4]      = Wa4[i];
            sW4[k * 64 + 32 + e4] = Wg4[i];
        }
    }
    if (tid < EE) { sb[tid] = ba[tid]; sb[EE + tid] = bg[tid]; }

    // x part (k=0,1)
    if (tid < ROWS * 2) {
        int r = tid >> 1, k = tid & 1;
        int n = n0 + r;
        sInp[k * ISR + r] = (n < NNODE) ? x[(((long)b * TT + t) * NNODE + n) * 2 + k] : 0.f;
    }
    // state part (k=2..65)
    for (int i = tid; i < ROWS * HH; i += 256) {
        int h = i & (HH - 1);
        int r = i >> 6;
        int n = n0 + r;
        float v = 0.f;
        if (n < NNODE) v = state_base[(long)b * bstride + (long)n * HH + h];
        sInp[(2 + h) * ISR + r] = v;
    }
    __syncthreads();

    const int cg = tid & 63, rg = tid >> 6;
    const int col0 = cg * 4;
    const int row0 = rg * 16;

    unsigned long long acc[8][4];
    #pragma unroll
    for (int p = 0; p < 8; p++)
        #pragma unroll
        for (int c = 0; c < 4; c++) acc[p][c] = 0ull;

    const float* sWp = sW + col0;
    const float* sIp = sInp + row0;

    #pragma unroll 2
    for (int k = 0; k < KK; k++) {
        float4 w4 = *(const float4*)(sWp + k * 256);
        unsigned long long w0 = pack2(w4.x, w4.x);
        unsigned long long w1 = pack2(w4.y, w4.y);
        unsigned long long w2 = pack2(w4.z, w4.z);
        unsigned long long w3 = pack2(w4.w, w4.w);
        const ulonglong2* ip = (const ulonglong2*)(sIp + k * ISR);
        #pragma unroll
        for (int q = 0; q < 4; q++) {
            ulonglong2 v = ip[q];        // rows (4q,4q+1) and (4q+2,4q+3)
            FFMA2(acc[2*q  ][0], v.x, w0);
            FFMA2(acc[2*q  ][1], v.x, w1);
            FFMA2(acc[2*q  ][2], v.x, w2);
            FFMA2(acc[2*q  ][3], v.x, w3);
            FFMA2(acc[2*q+1][0], v.y, w0);
            FFMA2(acc[2*q+1][1], v.y, w1);
            FFMA2(acc[2*q+1][2], v.y, w2);
            FFMA2(acc[2*q+1][3], v.y, w3);
        }
    }

    float4 bias = *(const float4*)(sb + col0);
    const int nb = n0 + row0;

    if (cg < 32) {   // res half: e = col0
        #pragma unroll
        for (int p = 0; p < 8; p++) {
            int n = nb + 2 * p;
            if (n < NNODE) {
                float4 o = make_float4(lo32(acc[p][0]) + bias.x, lo32(acc[p][1]) + bias.y,
                                       lo32(acc[p][2]) + bias.z, lo32(acc[p][3]) + bias.w);
                *(float4*)(g_res + ((long)b * NNODE + n) * EE + col0) = o;
            }
            if (n + 1 < NNODE) {
                float4 o = make_float4(hi32(acc[p][0]) + bias.x, hi32(acc[p][1]) + bias.y,
                                       hi32(acc[p][2]) + bias.z, hi32(acc[p][3]) + bias.w);
                *(float4*)(g_res + ((long)b * NNODE + n + 1) * EE + col0) = o;
            }
        }
    } else {         // h half: relu + row-sum -> g_agg
        int e0 = col0 - 128;
        int nmax = NNODE - nb;
        float s0 = 0.f, s1 = 0.f, s2 = 0.f, s3 = 0.f;
        #pragma unroll
        for (int p = 0; p < 8; p++) {
            if (2 * p < nmax) {
                s0 += fmaxf(lo32(acc[p][0]) + bias.x, 0.f);
                s1 += fmaxf(lo32(acc[p][1]) + bias.y, 0.f);
                s2 += fmaxf(lo32(acc[p][2]) + bias.z, 0.f);
                s3 += fmaxf(lo32(acc[p][3]) + bias.w, 0.f);
            }
            if (2 * p + 1 < nmax) {
                s0 += fmaxf(hi32(acc[p][0]) + bias.x, 0.f);
                s1 += fmaxf(hi32(acc[p][1]) + bias.y, 0.f);
                s2 += fmaxf(hi32(acc[p][2]) + bias.z, 0.f);
                s3 += fmaxf(hi32(acc[p][3]) + bias.w, 0.f);
            }
        }
        atomicAdd(&g_agg[b * EE + 128 + e0 - 128 + 0], s0);   // = b*EE + e0
        atomicAdd(&g_agg[b * EE + e0 + 1], s1);
        atomicAdd(&g_agg[b * EE + e0 + 2], s2);
        atomicAdd(&g_agg[b * EE + e0 + 3], s3);
    }
}

// ---------------- Kernel B: z-combine -> cand GEMMs + agg2 ----------------
// Block tile: 64 rows x 128 cols (cols 0-63: res2 via Wa, 64-127: h2 via Wg).
// 128 threads: cg = tid&31 -> col0 = 4*cg, rg = tid>>5 -> row0 = 16*rg.
extern "C" __global__ void __launch_bounds__(128, 4)
upd_mm_kernel(const float* __restrict__ x,
              const float* __restrict__ state_base, long bstride,
              const float* __restrict__ g_aff_w, const float* __restrict__ g_aff_b,
              const float* __restrict__ g_node_w, const float* __restrict__ g_add_w,
              const float* __restrict__ Wa, const float* __restrict__ ba,
              const float* __restrict__ Wg, const float* __restrict__ bg,
              int t)
{
    extern __shared__ float smem[];
    float* sW   = smem;                 // 66 * 128 = 8448 floats [k][c]
    float* sb   = sW + KK * 128;        // 128
    float* sagg = sb + 128;             // 64
    float* sS   = sagg + 64;            // 64
    float* sInp = sS + 64;              // 66 * 68 floats (offset 8704: 16B aligned)

    const int tid = threadIdx.x;
    const int b   = blockIdx.y;
    const int n0  = blockIdx.x * ROWS;

    {
        const float4* Wa4 = (const float4*)Wa;
        const float4* Wg4 = (const float4*)Wg;
        float4* sW4 = (float4*)sW;                 // row = 32 float4
        for (int i = tid; i < KK * HH / 4; i += 128) {
            int k = i >> 4, e4 = i & 15;
            sW4[k * 32 + e4]      = Wa4[i];
            sW4[k * 32 + 16 + e4] = Wg4[i];
        }
    }
    if (tid < HH) { sb[tid] = ba[tid]; sb[HH + tid] = bg[tid]; sagg[tid] = g_agg[b * EE + tid]; }
    else {
        int r = tid - HH;                        // 0..63
        int n = n0 + r;
        sS[r] = (n < NNODE) ? g_add_w[n] * g_node_w[n] : 0.f;
    }
    // x part
    {
        int r = tid >> 1, k = tid & 1;           // 128 threads cover 64 rows x 2
        int n = n0 + r;
        sInp[k * ISR + r] = (n < NNODE) ? x[(((long)b * TT + t) * NNODE + n) * 2 + k] : 0.f;
    }
    __syncthreads();

    // cand state part: z * state
    for (int i = tid; i < ROWS * HH; i += 128) {
        int h = i & (HH - 1);
        int r = i >> 6;
        int n = n0 + r;
        float v = 0.f;
        if (n < NNODE) {
            long m = (long)b * NNODE + n;
            float pre = g_res[m * EE + h]
                      + g_aff_w[(long)n * EE + h] * (sS[r] * sagg[h])
                      + g_aff_b[(long)n * EE + h];
            float z = 1.f / (1.f + __expf(-pre));
            v = z * state_base[(long)b * bstride + (long)n * HH + h];
        }
        sInp[(2 + h) * ISR + r] = v;
    }
    __syncthreads();

    const int cg = tid & 31, rg = tid >> 5;
    const int col0 = cg * 4;
    const int row0 = rg * 16;

    unsigned long long acc[8][4];
    #pragma unroll
    for (int p = 0; p < 8; p++)
        #pragma unroll
        for (int c = 0; c < 4; c++) acc[p][c] = 0ull;

    const float* sWp = sW + col0;
    const float* sIp = sInp + row0;

    #pragma unroll 2
    for (int k = 0; k < KK; k++) {
        float4 w4 = *(const float4*)(sWp + k * 128);
        unsigned long long w0 = pack2(w4.x, w4.x);
        unsigned long long w1 = pack2(w4.y, w4.y);
        unsigned long long w2 = pack2(w4.z, w4.z);
        unsigned long long w3 = pack2(w4.w, w4.w);
        const ulonglong2* ip = (const ulonglong2*)(sIp + k * ISR);
        #pragma unroll
        for (int q = 0; q < 4; q++) {
            ulonglong2 v = ip[q];
            FFMA2(acc[2*q  ][0], v.x, w0);
            FFMA2(acc[2*q  ][1], v.x, w1);
            FFMA2(acc[2*q  ][2], v.x, w2);
            FFMA2(acc[2*q  ][3], v.x, w3);
            FFMA2(acc[2*q+1][0], v.y, w0);
            FFMA2(acc[2*q+1][1], v.y, w1);
            FFMA2(acc[2*q+1][2], v.y, w2);
            FFMA2(acc[2*q+1][3], v.y, w3);
        }
    }

    float4 bias = *(const float4*)(sb + col0);
    const int nb = n0 + row0;

    if (cg < 16) {   // res2 half: e = col0
        #pragma unroll
        for (int p = 0; p < 8; p++) {
            int n = nb + 2 * p;
            if (n < NNODE) {
                float4 o = make_float4(lo32(acc[p][0]) + bias.x, lo32(acc[p][1]) + bias.y,
                                       lo32(acc[p][2]) + bias.z, lo32(acc[p][3]) + bias.w);
                *(float4*)(u_res + ((long)b * NNODE + n) * HH + col0) = o;
            }
            if (n + 1 < NNODE) {
                float4 o = make_float4(hi32(acc[p][0]) + bias.x, hi32(acc[p][1]) + bias.y,
                                       hi32(acc[p][2]) + bias.z, hi32(acc[p][3]) + bias.w);
                *(float4*)(u_res + ((long)b * NNODE + n + 1) * HH + col0) = o;
            }
        }
    } else {
        int e0 = col0 - 64;
        int nmax = NNODE - nb;
        float s0 = 0.f, s1 = 0.f, s2 = 0.f, s3 = 0.f;
        #pragma unroll
        for (int p = 0; p < 8; p++) {
            if (2 * p < nmax) {
                s0 += fmaxf(lo32(acc[p][0]) + bias.x, 0.f);
                s1 += fmaxf(lo32(acc[p][1]) + bias.y, 0.f);
                s2 += fmaxf(lo32(acc[p][2]) + bias.z, 0.f);
                s3 += fmaxf(lo32(acc[p][3]) + bias.w, 0.f);
            }
            if (2 * p + 1 < nmax) {
                s0 += fmaxf(hi32(acc[p][0]) + bias.x, 0.f);
                s1 += fmaxf(hi32(acc[p][1]) + bias.y, 0.f);
                s2 += fmaxf(hi32(acc[p][2]) + bias.z, 0.f);
                s3 += fmaxf(hi32(acc[p][3]) + bias.w, 0.f);
            }
        }
        atomicAdd(&u_agg[b * HH + e0 + 0], s0);
        atomicAdd(&u_agg[b * HH + e0 + 1], s1);
        atomicAdd(&u_agg[b * HH + e0 + 2], s2);
        atomicAdd(&u_agg[b * HH + e0 + 3], s3);
    }
}

// ---------------- Kernel C: final combine + output write (4 h per thread) ----------------
extern "C" __global__ void __launch_bounds__(256)
combine_kernel(const float* __restrict__ state_base, long bstride,
               const float* __restrict__ g_aff_w, const float* __restrict__ g_aff_b,
               const float* __restrict__ g_node_w, const float* __restrict__ g_add_w,
               const float* __restrict__ u_aff_w, const float* __restrict__ u_aff_b,
               const float* __restrict__ u_node_w, const float* __restrict__ u_add_w,
               float* __restrict__ out, int t)
{
    int i = blockIdx.x * 256 + threadIdx.x;          // i in [0, N * H/4)
    if (i >= NNODE * (HH / 4)) return;
    const int b = blockIdx.y;
    const int n = i >> 4;
    const int h = (i & 15) * 4;

    const long m = (long)b * NNODE + n;

    float sg = g_add_w[n] * g_node_w[n];
    float su = u_add_w[n] * u_node_w[n];

    float4 gr  = *(const float4*)(g_res   + m * EE + HH + h);
    float4 gaw = *(const float4*)(g_aff_w + (long)n * EE + HH + h);
    float4 gab = *(const float4*)(g_aff_b + (long)n * EE + HH + h);
    float4 gag = *(const float4*)(g_agg   + b * EE + HH + h);

    float4 ur  = *(const float4*)(u_res   + m * HH + h);
    float4 uaw = *(const float4*)(u_aff_w + (long)n * HH + h);
    float4 uab = *(const float4*)(u_aff_b + (long)n * HH + h);
    float4 uag = *(const float4*)(u_agg   + b * HH + h);

    float4 st  = *(const float4*)(state_base + (long)b * bstride + (long)n * HH + h);

    float4 hn;
    {
        float rp, r, hcp, hc;
        rp = gr.x + gaw.x * (sg * gag.x) + gab.x; r = 1.f / (1.f + __expf(-rp));
        hcp = ur.x + uaw.x * (su * uag.x) + uab.x; hc = tanhf(hcp);
        hn.x = r * st.x + (1.f - r) * hc;
        rp = gr.y + gaw.y * (sg * gag.y) + gab.y; r = 1.f / (1.f + __expf(-rp));
        hcp = ur.y + uaw.y * (su * uag.y) + uab.y; hc = tanhf(hcp);
        hn.y = r * st.y + (1.f - r) * hc;
        rp = gr.z + gaw.z * (sg * gag.z) + gab.z; r = 1.f / (1.f + __expf(-rp));
        hcp = ur.z + uaw.z * (su * uag.z) + uab.z; hc = tanhf(hcp);
        hn.z = r * st.z + (1.f - r) * hc;
        rp = gr.w + gaw.w * (sg * gag.w) + gab.w; r = 1.f / (1.f + __expf(-rp));
        hcp = ur.w + uaw.w * (su * uag.w) + uab.w; hc = tanhf(hcp);
        hn.w = r * st.w + (1.f - r) * hc;
    }

    *(float4*)(out + (((long)b * TT + t) * NNODE + n) * HH + h) = hn;
    if (t == TT - 1)
        *(float4*)(out + (long)BB * TT * NNODE * HH + m * HH + h) = hn;
}

// ---------------- launch ----------------
extern "C" void kernel_launch(void* const* d_in, const int* in_sizes, int n_in,
                              void* d_out, int out_size)
{
    const float* x            = (const float*)d_in[0];
    const float* init_state   = (const float*)d_in[1];
    const float* gate_align_w = (const float*)d_in[4];
    const float* gate_align_b = (const float*)d_in[5];
    const float* gate_w       = (const float*)d_in[6];
    const float* gate_b       = (const float*)d_in[7];
    const float* gate_node_w  = (const float*)d_in[8];
    const float* gate_add_w   = (const float*)d_in[9];
    const float* gate_aff_w   = (const float*)d_in[10];
    const float* gate_aff_b   = (const float*)d_in[11];
    const float* upd_align_w  = (const float*)d_in[12];
    const float* upd_align_b  = (const float*)d_in[13];
    const float* upd_w        = (const float*)d_in[14];
    const float* upd_b        = (const float*)d_in[15];
    const float* upd_node_w   = (const float*)d_in[16];
    const float* upd_add_w    = (const float*)d_in[17];
    const float* upd_aff_w    = (const float*)d_in[18];
    const float* upd_aff_b    = (const float*)d_in[19];
    float* out = (float*)d_out;

    const int smemA = (KK * 256 + 256 + KK * ISR) * (int)sizeof(float);              // 86,560 B
    const int smemB = (KK * 128 + 128 + 64 + 64 + KK * ISR) * (int)sizeof(float);    // 52,768 B
    cudaFuncSetAttribute(gate_mm_kernel, cudaFuncAttributeMaxDynamicSharedMemorySize, smemA);
    cudaFuncSetAttribute(upd_mm_kernel,  cudaFuncAttributeMaxDynamicSharedMemorySize, smemB);

    dim3 gridMM((NNODE + ROWS - 1) / ROWS, BB);                   // (135, 16)
    dim3 gridC((NNODE * (HH / 4) + 255) / 256, BB);               // (538, 16)

    for (int t = 0; t < TT; t++) {
        const float* sb_ = (t == 0) ? init_state : (out + (long)(t - 1) * NNODE * HH);
        long bstride     = (t == 0) ? (long)NNODE * HH : (long)TT * NNODE * HH;

        zero_agg_kernel<<<(BB * EE + 255) / 256, 256>>>();

        gate_mm_kernel<<<gridMM, 256, smemA>>>(x, sb_, bstride,
                                               gate_align_w, gate_align_b,
                                               gate_w, gate_b, t);

        upd_mm_kernel<<<gridMM, 128, smemB>>>(x, sb_, bstride,
                                              gate_aff_w, gate_aff_b, gate_node_w, gate_add_w,
                                              upd_align_w, upd_align_b, upd_w, upd_b, t);

        combine_kernel<<<gridC, 256>>>(sb_, bstride,
                                       gate_aff_w, gate_aff_b, gate_node_w, gate_add_w,
                                       upd_aff_w, upd_aff_b, upd_node_w, upd_add_w,
                                       out, t);
    }
}